// round 10
// baseline (speedup 1.0000x reference)
#include <cuda_runtime.h>
#include <cuda_bf16.h>
#include <math.h>

#define N_TAGS 48
#define ROOT 46
#define END_TAG 47
#define BATCH 512
#define MAXT 256
#define PF 4            // prefetch depth (per tag column): 8 LDGs in flight
#define WARPS 12        // warps per CTA: 3 per SMSP on all 4 SMSPs

typedef unsigned long long ull;

__device__ __forceinline__ ull fma2(ull a, ull b, ull c) {
    ull d;
    asm("fma.rn.f32x2 %0, %1, %2, %3;" : "=l"(d) : "l"(a), "l"(b), "l"(c));
    return d;
}
__device__ __forceinline__ ull add2(ull a, ull b) {
    ull d;
    asm("add.rn.f32x2 %0, %1, %2;" : "=l"(d) : "l"(a), "l"(b));
    return d;
}
__device__ __forceinline__ ull pack2(float lo, float hi) {
    ull d;
    asm("mov.b64 %0, {%1, %2};" : "=l"(d) : "f"(lo), "f"(hi));
    return d;
}
__device__ __forceinline__ float sum2(ull a) {
    float lo, hi;
    asm("mov.b64 {%0, %1}, %2;" : "=f"(lo), "=f"(hi) : "l"(a));
    return lo + hi;
}

__global__ __launch_bounds__(32 * WARPS)
void crf_nll_kernel(const float* __restrict__ feats,
                    const int* __restrict__ tags,
                    const int* __restrict__ lengths,
                    const float* __restrict__ lt,
                    float* __restrict__ out)
{
    const int w = threadIdx.x >> 5;         // warp in block -> SMSP w%4
    const int j = threadIdx.x & 31;         // lane 0..31
    const int b = blockIdx.x * WARPS + w;   // one batch per warp
    if (b >= BATCH) return;                 // surplus warps exit (warp-uniform)
    const bool hasB = (j < 16);             // lane also owns tag 32+j

    // per-warp double-buffered r vectors (16B-aligned slices)
    __shared__ __align__(16) float se[WARPS][2][N_TAGS];

    const int len = lengths[b];
    const long fbase = (long)b * MAXT * N_TAGS;
    const int tbase = b * MAXT;

    // ---------------- gold score (32 threads, t-strided) ----------------
    float gold;
    {
        float g = 0.0f;
        for (int t = j; t < MAXT; t += 32) {
            if (t < len) {
                int tg = tags[tbase + t];
                g += feats[fbase + t * N_TAGS + tg];
                if (t >= 1) {
                    int tp = tags[tbase + t - 1];
                    g += lt[tp * N_TAGS + tg];
                }
            }
        }
        if (j == 0) {
            int t0 = tags[tbase];
            int tl = tags[tbase + len - 1];
            g += lt[ROOT * N_TAGS + t0] + lt[tl * N_TAGS + END_TAG];
        }
        #pragma unroll
        for (int off = 16; off; off >>= 1)
            g += __shfl_xor_sync(0xffffffffu, g, off);
        gold = g;   // every lane has it
    }

    // ---------------- packed E columns in registers -------------------------
    ull EPa[N_TAGS / 2], EPb[N_TAGS / 2];
    #pragma unroll
    for (int k = 0; k < N_TAGS / 2; k++) {
        float lo = __expf(lt[(2 * k) * N_TAGS + j]);
        float hi = __expf(lt[(2 * k + 1) * N_TAGS + j]);
        EPa[k] = pack2(lo, hi);
        float lob = hasB ? __expf(lt[(2 * k) * N_TAGS + 32 + j]) : 0.0f;
        float hib = hasB ? __expf(lt[(2 * k + 1) * N_TAGS + 32 + j]) : 0.0f;
        EPb[k] = pack2(lob, hib);
    }

    const float lt_end_a = lt[j * N_TAGS + END_TAG];
    const float lt_end_b = hasB ? lt[(32 + j) * N_TAGS + END_TAG] : 0.0f;

    // ---------------- init: S_0 = alpha_0(0); r_j(0) = exp(alpha_j(0)-S) ----
    float S = lt[ROOT * N_TAGS + 0] + feats[fbase + 0];   // same in all lanes
    float r_a = __expf(lt[ROOT * N_TAGS + j] + feats[fbase + j] - S);
    float r_b = hasB ? __expf(lt[ROOT * N_TAGS + 32 + j] + feats[fbase + 32 + j] - S)
                     : 0.0f;

    // ---------------- feats prefetch pipeline ----------------
    float fa[PF], fb[PF];
    #pragma unroll
    for (int d = 0; d < PF; d++) {
        int t = 1 + d;
        fa[d] = feats[fbase + (long)t * N_TAGS + j];
        fb[d] = hasB ? feats[fbase + (long)t * N_TAGS + 32 + j] : 0.0f;
    }

    // publish r(0)
    se[w][0][j] = r_a;
    if (hasB) se[w][0][32 + j] = r_b;
    __syncwarp();

    // ---------------- forward recurrence: branch-free masked step body ------
    // Chunk loop exits early (uniform, chunk granularity); inside a chunk all
    // PF steps execute unconditionally, with state updates masked by (t<len),
    // mirroring the reference's alpha-freeze semantics.
    int cur = 0;
    for (int t0 = 1; t0 < len; t0 += PF) {
        #pragma unroll
        for (int d = 0; d < PF; d++) {
            const int t = t0 + d;
            const bool upd = (t < len);          // uniform mask

            float fca = fa[d], fcb = fb[d];
            float f0 = __shfl_sync(0xffffffffu, fca, 0);   // f_0(t)

            const int tpre = t + PF;
            if (tpre < MAXT) {                   // uniform predicated LDG
                fa[d] = feats[fbase + (long)tpre * N_TAGS + j];
                fb[d] = hasB ? feats[fbase + (long)tpre * N_TAGS + 32 + j] : fb[d];
            }

            // renormalizer from PREVIOUS step's published r_0 — overlaps dot
            float r0prev = se[w][cur][0];
            float c = __logf(r0prev) + f0;
            float ea = __expf(fca - c);
            float eb = __expf(fcb - c);

            // packed dot: 24 fma.rn.f32x2 per output column
            const ulonglong2* se2 = (const ulonglong2*)se[w][cur];
            ull a0 = 0, a1 = 0, a2 = 0, a3 = 0;   // bit pattern 0 == (0,0)
            ull b0 = 0, b1 = 0, b2 = 0, b3 = 0;
            #pragma unroll
            for (int i = 0; i < 12; i += 2) {
                ulonglong2 w0 = se2[i];
                ulonglong2 w1 = se2[i + 1];
                a0 = fma2(w0.x, EPa[2 * i + 0], a0);
                a1 = fma2(w0.y, EPa[2 * i + 1], a1);
                a2 = fma2(w1.x, EPa[2 * i + 2], a2);
                a3 = fma2(w1.y, EPa[2 * i + 3], a3);
                b0 = fma2(w0.x, EPb[2 * i + 0], b0);
                b1 = fma2(w0.y, EPb[2 * i + 1], b1);
                b2 = fma2(w1.x, EPb[2 * i + 2], b2);
                b3 = fma2(w1.y, EPb[2 * i + 3], b3);
            }
            float sa = sum2(add2(add2(a0, a1), add2(a2, a3)));
            float sb = sum2(add2(add2(b0, b1), add2(b2, b3)));

            // masked multiplicative update (selects, no branches)
            r_a = upd ? (sa * ea) : r_a;
            r_b = upd ? (sb * eb) : r_b;
            S   = upd ? (S + c)   : S;

            se[w][cur ^ 1][j] = r_a;
            if (hasB) se[w][cur ^ 1][32 + j] = r_b;
            __syncwarp();

            cur ^= 1;
        }
    }

    // ---------------- partition = lse over 48 terminal scores ----------------
    // alpha_j(T) = S + log(r_j)
    float pa = S + __logf(r_a) + lt_end_a;
    float pb = hasB ? (S + __logf(r_b) + lt_end_b) : -INFINITY;
    float m = fmaxf(pa, pb);
    #pragma unroll
    for (int off = 16; off; off >>= 1)
        m = fmaxf(m, __shfl_xor_sync(0xffffffffu, m, off));

    float ex = __expf(pa - m) + (hasB ? __expf(pb - m) : 0.0f);
    #pragma unroll
    for (int off = 16; off; off >>= 1)
        ex += __shfl_xor_sync(0xffffffffu, ex, off);

    if (j == 0)
        out[b] = m + __logf(ex) - gold;
}

extern "C" void kernel_launch(void* const* d_in, const int* in_sizes, int n_in,
                              void* d_out, int out_size)
{
    const float* feats = nullptr;
    const int*   tags = nullptr;
    const int*   lengths = nullptr;
    const float* lt = nullptr;

    for (int i = 0; i < n_in; i++) {
        switch (in_sizes[i]) {
            case BATCH * MAXT * N_TAGS: feats   = (const float*)d_in[i]; break;
            case BATCH * MAXT:          tags    = (const int*)d_in[i];   break;
            case BATCH:                 lengths = (const int*)d_in[i];   break;
            case N_TAGS * N_TAGS:       lt      = (const float*)d_in[i]; break;
        }
    }

    const int grid = (BATCH + WARPS - 1) / WARPS;   // 43
    crf_nll_kernel<<<grid, 32 * WARPS>>>(feats, tags, lengths, lt, (float*)d_out);
}

// round 11
// speedup vs baseline: 1.2703x; 1.2703x over previous
#include <cuda_runtime.h>
#include <cuda_bf16.h>
#include <math.h>

#define N_TAGS 48
#define ROOT 46
#define END_TAG 47
#define BATCH 512
#define MAXT 256
#define PF 4            // prefetch depth (per tag column): 8 LDGs in flight
#define WARPS 4         // one batch per warp; 1 warp per SMSP, 128 SMs busy

typedef unsigned long long ull;

__device__ __forceinline__ ull fma2(ull a, ull b, ull c) {
    ull d;
    asm("fma.rn.f32x2 %0, %1, %2, %3;" : "=l"(d) : "l"(a), "l"(b), "l"(c));
    return d;
}
__device__ __forceinline__ ull add2(ull a, ull b) {
    ull d;
    asm("add.rn.f32x2 %0, %1, %2;" : "=l"(d) : "l"(a), "l"(b));
    return d;
}
__device__ __forceinline__ ull pack2(float lo, float hi) {
    ull d;
    asm("mov.b64 %0, {%1, %2};" : "=l"(d) : "f"(lo), "f"(hi));
    return d;
}
__device__ __forceinline__ float sum2(ull a) {
    float lo, hi;
    asm("mov.b64 {%0, %1}, %2;" : "=f"(lo), "=f"(hi) : "l"(a));
    return lo + hi;
}
__device__ __forceinline__ float frcp(float x) {
    float y;
    asm("rcp.approx.f32 %0, %1;" : "=f"(y) : "f"(x));
    return y;
}

__global__ __launch_bounds__(32 * WARPS)
void crf_nll_kernel(const float* __restrict__ feats,
                    const int* __restrict__ tags,
                    const int* __restrict__ lengths,
                    const float* __restrict__ lt,
                    float* __restrict__ out)
{
    const int w = threadIdx.x >> 5;         // warp in block -> SMSP w
    const int j = threadIdx.x & 31;         // lane 0..31
    const int b = blockIdx.x * WARPS + w;   // one batch per warp
    const bool hasB = (j < 16);             // lane also owns tag 32+j

    __shared__ __align__(16) float se[WARPS][2][N_TAGS];

    const int len = lengths[b];
    const long fbase = (long)b * MAXT * N_TAGS;
    const int tbase = b * MAXT;

    // ---------------- gold score (32 threads, t-strided) ----------------
    float gold;
    {
        float g = 0.0f;
        for (int t = j; t < MAXT; t += 32) {
            if (t < len) {
                int tg = tags[tbase + t];
                g += feats[fbase + t * N_TAGS + tg];
                if (t >= 1) {
                    int tp = tags[tbase + t - 1];
                    g += lt[tp * N_TAGS + tg];
                }
            }
        }
        if (j == 0) {
            int t0 = tags[tbase];
            int tl = tags[tbase + len - 1];
            g += lt[ROOT * N_TAGS + t0] + lt[tl * N_TAGS + END_TAG];
        }
        #pragma unroll
        for (int off = 16; off; off >>= 1)
            g += __shfl_xor_sync(0xffffffffu, g, off);
        gold = g;
    }

    // ---------------- packed E columns in registers -------------------------
    ull EPa[N_TAGS / 2], EPb[N_TAGS / 2];
    #pragma unroll
    for (int k = 0; k < N_TAGS / 2; k++) {
        float lo = __expf(lt[(2 * k) * N_TAGS + j]);
        float hi = __expf(lt[(2 * k + 1) * N_TAGS + j]);
        EPa[k] = pack2(lo, hi);
        float lob = hasB ? __expf(lt[(2 * k) * N_TAGS + 32 + j]) : 0.0f;
        float hib = hasB ? __expf(lt[(2 * k + 1) * N_TAGS + 32 + j]) : 0.0f;
        EPb[k] = pack2(lob, hib);
    }

    const float lt_end_a = lt[j * N_TAGS + END_TAG];
    const float lt_end_b = hasB ? lt[(32 + j) * N_TAGS + END_TAG] : 0.0f;

    // ---------------- init: S_0 = alpha_0(0); r_j(0) = exp(alpha_j(0)-S) ----
    float S = lt[ROOT * N_TAGS + 0] + feats[fbase + 0];
    float r_a = __expf(lt[ROOT * N_TAGS + j] + feats[fbase + j] - S);
    float r_b = hasB ? __expf(lt[ROOT * N_TAGS + 32 + j] + feats[fbase + 32 + j] - S)
                     : 0.0f;

    // ---------------- raw feats prefetch pipeline ----------------
    float fa[PF], fb[PF];
    #pragma unroll
    for (int d = 0; d < PF; d++) {
        int t = 1 + d;
        fa[d] = feats[fbase + (long)t * N_TAGS + j];
        fb[d] = hasB ? feats[fbase + (long)t * N_TAGS + 32 + j] : 0.0f;
    }

    // exp(feats) for the FIRST loop step, computed up front; thereafter each
    // step computes the NEXT step's exps (a full step of slack, off-path)
    float ef_a = __expf(fa[0]);
    float ef_b = __expf(fb[0]);

    // publish r(0)
    se[w][0][j] = r_a;
    if (hasB) se[w][0][32 + j] = r_b;
    __syncwarp();

    int cur = 0;

    // ================= step body (macro-ish lambda) ========================
    auto step = [&](int t, int d, int dn, bool masked) {
        const bool upd = !masked || (t < len);

        float fra = fa[d];
        float f0 = __shfl_sync(0xffffffffu, fra, 0);    // raw f_0(t), off-path
        float ea = ef_a;                                // exp(f_j(t)), ready
        float eb = ef_b;
        float e0 = __shfl_sync(0xffffffffu, ea, 0);     // exp(f_0(t))

        // refill this slot with t+PF
        const int tpre = t + PF;
        if (tpre < MAXT) {
            fa[d] = feats[fbase + (long)tpre * N_TAGS + j];
            fb[d] = hasB ? feats[fbase + (long)tpre * N_TAGS + 32 + j] : fb[d];
        }

        // next step's exps (slot dn holds t+1's raw feats, long arrived)
        ef_a = __expf(fa[dn]);
        ef_b = __expf(fb[dn]);

        // normalizer: inv = 1/(r0prev * e0); rcp chain hides under the dot
        float r0prev = se[w][cur][0];
        float inv = frcp(r0prev * e0);
        float ka = ea * inv;                            // per-lane scale
        float kb = eb * inv;

        // S side-chain (log fully off the r-recurrence path)
        float c = __logf(r0prev) + f0;

        // packed dot: 24 fma.rn.f32x2 per output column
        const ulonglong2* se2 = (const ulonglong2*)se[w][cur];
        ull a0 = 0, a1 = 0, a2 = 0, a3 = 0;
        ull b0 = 0, b1 = 0, b2 = 0, b3 = 0;
        #pragma unroll
        for (int i = 0; i < 12; i += 2) {
            ulonglong2 w0 = se2[i];
            ulonglong2 w1 = se2[i + 1];
            a0 = fma2(w0.x, EPa[2 * i + 0], a0);
            a1 = fma2(w0.y, EPa[2 * i + 1], a1);
            a2 = fma2(w1.x, EPa[2 * i + 2], a2);
            a3 = fma2(w1.y, EPa[2 * i + 3], a3);
            b0 = fma2(w0.x, EPb[2 * i + 0], b0);
            b1 = fma2(w0.y, EPb[2 * i + 1], b1);
            b2 = fma2(w1.x, EPb[2 * i + 2], b2);
            b3 = fma2(w1.y, EPb[2 * i + 3], b3);
        }
        float sa = sum2(add2(add2(a0, a1), add2(a2, a3)));
        float sb = sum2(add2(add2(b0, b1), add2(b2, b3)));

        r_a = upd ? (sa * ka) : r_a;
        r_b = upd ? (sb * kb) : r_b;
        S   = upd ? (S + c)   : S;

        se[w][cur ^ 1][j] = r_a;
        if (hasB) se[w][cur ^ 1][32 + j] = r_b;
        __syncwarp();
        cur ^= 1;
    };

    // ---------------- main loop: full chunks, no masking -------------------
    int t0 = 1;
    for (; t0 + PF <= len; t0 += PF) {
        #pragma unroll
        for (int d = 0; d < PF; d++)
            step(t0 + d, d, (d + 1) & (PF - 1), false);
    }
    // ---------------- masked tail chunk ------------------------------------
    if (t0 < len) {
        #pragma unroll
        for (int d = 0; d < PF; d++)
            step(t0 + d, d, (d + 1) & (PF - 1), true);
    }

    // ---------------- partition = lse over 48 terminal scores ----------------
    float pa = S + __logf(r_a) + lt_end_a;
    float pb = hasB ? (S + __logf(r_b) + lt_end_b) : -INFINITY;
    float m = fmaxf(pa, pb);
    #pragma unroll
    for (int off = 16; off; off >>= 1)
        m = fmaxf(m, __shfl_xor_sync(0xffffffffu, m, off));

    float ex = __expf(pa - m) + (hasB ? __expf(pb - m) : 0.0f);
    #pragma unroll
    for (int off = 16; off; off >>= 1)
        ex += __shfl_xor_sync(0xffffffffu, ex, off);

    if (j == 0)
        out[b] = m + __logf(ex) - gold;
}

extern "C" void kernel_launch(void* const* d_in, const int* in_sizes, int n_in,
                              void* d_out, int out_size)
{
    const float* feats = nullptr;
    const int*   tags = nullptr;
    const int*   lengths = nullptr;
    const float* lt = nullptr;

    for (int i = 0; i < n_in; i++) {
        switch (in_sizes[i]) {
            case BATCH * MAXT * N_TAGS: feats   = (const float*)d_in[i]; break;
            case BATCH * MAXT:          tags    = (const int*)d_in[i];   break;
            case BATCH:                 lengths = (const int*)d_in[i];   break;
            case N_TAGS * N_TAGS:       lt      = (const float*)d_in[i]; break;
        }
    }

    crf_nll_kernel<<<BATCH / WARPS, 32 * WARPS>>>(feats, tags, lengths, lt, (float*)d_out);
}

// round 12
// speedup vs baseline: 1.8131x; 1.4273x over previous
#include <cuda_runtime.h>
#include <cuda_bf16.h>
#include <math.h>

#define N_TAGS 48
#define ROOT 46
#define END_TAG 47
#define BATCH 512
#define MAXT 256
#define WARPS 4         // 4 sequences per CTA, one per warp/SMSP

typedef unsigned long long ull;

// dynamic smem layout:
//   feats_s : float[WARPS][MAXT][N_TAGS]   (192 KB)
//   se      : float[WARPS][2][N_TAGS]      (1.5 KB, 16B aligned)
#define FEATS_ELEMS (WARPS * MAXT * N_TAGS)
#define SMEM_BYTES  (FEATS_ELEMS * 4 + WARPS * 2 * N_TAGS * 4)

__device__ __forceinline__ ull fma2(ull a, ull b, ull c) {
    ull d;
    asm("fma.rn.f32x2 %0, %1, %2, %3;" : "=l"(d) : "l"(a), "l"(b), "l"(c));
    return d;
}
__device__ __forceinline__ ull add2(ull a, ull b) {
    ull d;
    asm("add.rn.f32x2 %0, %1, %2;" : "=l"(d) : "l"(a), "l"(b));
    return d;
}
__device__ __forceinline__ ull pack2(float lo, float hi) {
    ull d;
    asm("mov.b64 %0, {%1, %2};" : "=l"(d) : "f"(lo), "f"(hi));
    return d;
}
__device__ __forceinline__ float sum2(ull a) {
    float lo, hi;
    asm("mov.b64 {%0, %1}, %2;" : "=f"(lo), "=f"(hi) : "l"(a));
    return lo + hi;
}
__device__ __forceinline__ float frcp(float x) {
    float y;
    asm("rcp.approx.f32 %0, %1;" : "=f"(y) : "f"(x));
    return y;
}

__global__ __launch_bounds__(32 * WARPS)
void crf_nll_kernel(const float* __restrict__ feats,
                    const int* __restrict__ tags,
                    const int* __restrict__ lengths,
                    const float* __restrict__ lt,
                    float* __restrict__ out)
{
    extern __shared__ __align__(16) char smem_raw[];
    float* feats_s = (float*)smem_raw;                                   // [WARPS][MAXT][N_TAGS]
    float (*se)[2][N_TAGS] = (float (*)[2][N_TAGS])(smem_raw + FEATS_ELEMS * 4);

    const int w = threadIdx.x >> 5;         // warp -> SMSP w
    const int j = threadIdx.x & 31;         // lane
    const int jb = 32 + (j & 15);           // b-column (lanes 16-31 mirror 0-15)
    const int b = blockIdx.x * WARPS + w;   // one batch per warp
    const bool hasB = (j < 16);

    // ---------------- stage ALL feats for this CTA into smem ----------------
    // global region is contiguous: feats[b0*MAXT*N_TAGS ... +4*MAXT*N_TAGS)
    {
        const float4* src4 = (const float4*)(feats + (long)blockIdx.x * FEATS_ELEMS);
        float4* dst4 = (float4*)feats_s;
        #pragma unroll 4
        for (int i = threadIdx.x; i < FEATS_ELEMS / 4; i += 32 * WARPS)
            dst4[i] = src4[i];
    }
    __syncthreads();

    float* F = feats_s + w * MAXT * N_TAGS;     // this warp's sequence
    const int len = lengths[b];
    const int tbase = b * MAXT;

    // ---------------- gold score (32 threads, t-strided; feats from smem) ---
    float gold;
    {
        float g = 0.0f;
        for (int t = j; t < MAXT; t += 32) {
            if (t < len) {
                int tg = tags[tbase + t];
                g += F[t * N_TAGS + tg];
                if (t >= 1) {
                    int tp = tags[tbase + t - 1];
                    g += lt[tp * N_TAGS + tg];
                }
            }
        }
        if (j == 0) {
            int t0 = tags[tbase];
            int tl = tags[tbase + len - 1];
            g += lt[ROOT * N_TAGS + t0] + lt[tl * N_TAGS + END_TAG];
        }
        #pragma unroll
        for (int off = 16; off; off >>= 1)
            g += __shfl_xor_sync(0xffffffffu, g, off);
        gold = g;
    }

    // ---------------- packed E columns in registers -------------------------
    ull EPa[N_TAGS / 2], EPb[N_TAGS / 2];
    #pragma unroll
    for (int k = 0; k < N_TAGS / 2; k++) {
        float lo = __expf(lt[(2 * k) * N_TAGS + j]);
        float hi = __expf(lt[(2 * k + 1) * N_TAGS + j]);
        EPa[k] = pack2(lo, hi);
        float lob = hasB ? __expf(lt[(2 * k) * N_TAGS + jb]) : 0.0f;
        float hib = hasB ? __expf(lt[(2 * k + 1) * N_TAGS + jb]) : 0.0f;
        EPb[k] = pack2(lob, hib);
    }

    const float lt_end_a = lt[j * N_TAGS + END_TAG];
    const float lt_end_b = hasB ? lt[jb * N_TAGS + END_TAG] : 0.0f;

    // ---------------- init: S_0 = alpha_0(0); r_j(0) = exp(alpha_j(0)-S) ----
    float S = lt[ROOT * N_TAGS + 0] + F[0];
    float r_a = __expf(lt[ROOT * N_TAGS + j] + F[j] - S);
    float r_b = hasB ? __expf(lt[ROOT * N_TAGS + jb] + F[jb] - S) : 0.0f;

    // exp(feats(t=1)) precomputed; loop computes t+1's exps one step ahead
    float efa = __expf(F[N_TAGS + j]);
    float efb = __expf(F[N_TAGS + jb]);

    // publish r(0)
    se[w][0][j] = r_a;
    if (hasB) se[w][0][32 + j] = r_b;
    __syncwarp();

    // ---------------- forward recurrence: zero LDG, all-smem ---------------
    int cur = 0;
    for (int t = 1; t < len; ++t) {
        float ea = efa, eb = efb;                 // exp(f(t)), ready

        // lookahead: exp(f(t+1)) — LDS+MUFU fully off the r-recurrence path
        int tn = (t + 1 < MAXT) ? (t + 1) : 0;
        float fna = F[tn * N_TAGS + j];
        float fnb = F[tn * N_TAGS + jb];
        efa = __expf(fna);
        efb = __expf(fnb);

        // normalizer: inv = 1/(r0prev * e0); entire chain hides under the dot
        float e0 = __shfl_sync(0xffffffffu, ea, 0);    // ea ready at step start
        float r0prev = se[w][cur][0];                  // broadcast LDS
        float inv = frcp(r0prev * e0);
        float ka = ea * inv;
        float kb = eb * inv;

        // S side-chain (log + f0 off-path)
        float f0 = F[t * N_TAGS];                      // broadcast LDS
        float c = __logf(r0prev) + f0;

        // packed dot: 24 fma.rn.f32x2 per output column
        const ulonglong2* se2 = (const ulonglong2*)se[w][cur];
        ull a0 = 0, a1 = 0, a2 = 0, a3 = 0;
        ull b0 = 0, b1 = 0, b2 = 0, b3 = 0;
        #pragma unroll
        for (int i = 0; i < 12; i += 2) {
            ulonglong2 w0 = se2[i];
            ulonglong2 w1 = se2[i + 1];
            a0 = fma2(w0.x, EPa[2 * i + 0], a0);
            a1 = fma2(w0.y, EPa[2 * i + 1], a1);
            a2 = fma2(w1.x, EPa[2 * i + 2], a2);
            a3 = fma2(w1.y, EPa[2 * i + 3], a3);
            b0 = fma2(w0.x, EPb[2 * i + 0], b0);
            b1 = fma2(w0.y, EPb[2 * i + 1], b1);
            b2 = fma2(w1.x, EPb[2 * i + 2], b2);
            b3 = fma2(w1.y, EPb[2 * i + 3], b3);
        }
        float sa = sum2(add2(add2(a0, a1), add2(a2, a3)));
        float sb = sum2(add2(add2(b0, b1), add2(b2, b3)));

        r_a = sa * ka;
        r_b = sb * kb;
        S += c;

        se[w][cur ^ 1][j] = r_a;
        if (hasB) se[w][cur ^ 1][32 + j] = r_b;
        __syncwarp();
        cur ^= 1;
    }

    // ---------------- partition = lse over 48 terminal scores ----------------
    float pa = S + __logf(r_a) + lt_end_a;
    float pb = hasB ? (S + __logf(r_b) + lt_end_b) : -INFINITY;
    float m = fmaxf(pa, pb);
    #pragma unroll
    for (int off = 16; off; off >>= 1)
        m = fmaxf(m, __shfl_xor_sync(0xffffffffu, m, off));

    float ex = __expf(pa - m) + (hasB ? __expf(pb - m) : 0.0f);
    #pragma unroll
    for (int off = 16; off; off >>= 1)
        ex += __shfl_xor_sync(0xffffffffu, ex, off);

    if (j == 0)
        out[b] = m + __logf(ex) - gold;
}

extern "C" void kernel_launch(void* const* d_in, const int* in_sizes, int n_in,
                              void* d_out, int out_size)
{
    const float* feats = nullptr;
    const int*   tags = nullptr;
    const int*   lengths = nullptr;
    const float* lt = nullptr;

    for (int i = 0; i < n_in; i++) {
        switch (in_sizes[i]) {
            case BATCH * MAXT * N_TAGS: feats   = (const float*)d_in[i]; break;
            case BATCH * MAXT:          tags    = (const int*)d_in[i];   break;
            case BATCH:                 lengths = (const int*)d_in[i];   break;
            case N_TAGS * N_TAGS:       lt      = (const float*)d_in[i]; break;
        }
    }

    static bool attr_set = false;   // attribute config, not a guard on work
    if (!attr_set) {
        cudaFuncSetAttribute(crf_nll_kernel,
                             cudaFuncAttributeMaxDynamicSharedMemorySize,
                             SMEM_BYTES);
        attr_set = true;
    }

    crf_nll_kernel<<<BATCH / WARPS, 32 * WARPS, SMEM_BYTES>>>(
        feats, tags, lengths, lt, (float*)d_out);
}